// round 16
// baseline (speedup 1.0000x reference)
#include <cuda_runtime.h>
#include <math.h>

#define N_PTS 16384      // 128*128 spatial points
#define N_CH  512        // channels
#define NBATCH 4
#define THRV  0.01f
#define THRESH_INC 1536
#define NSEG 32          // c-splits in dots phase (16 channels each)
#define NBLK 512
#define NT   256

// ---------------- device state ----------------
__device__ float    g_invnorm[N_PTS];
__device__ float    g_nsqpart[NSEG * N_PTS];      // 2MB
__device__ float    g_dotpart[NSEG * 2 * N_PTS];  // 4MB [p][k][n]
__device__ float    g_cn[2 * N_CH];
__device__ float    g_centers[2 * N_CH];
__device__ float    g_sums[2 * N_CH];
__device__ float    g_cout[2 * N_CH];
__device__ float2   g_d[N_PTS];
__device__ int      g_lab[N_PTS];
__device__ unsigned g_labbits[NBLK];              // 1 word per 32 points
__device__ unsigned g_chgbits[NBLK];
__device__ float2   g_dsnap[NBATCH * N_PTS];
__device__ float    g_mn[8], g_mx[8];
__device__ float    g_cd, g_cini;
__device__ int      g_Ci, g_stable, g_nchanged, g_cnt1;
__device__ unsigned g_b1cnt, g_b1rel, g_b2cnt, g_b2rel, g_done;

// ---------------- init ----------------
__global__ void k_init(const float* __restrict__ CI) {
    int t = threadIdx.x;   // 512
    float v0 = CI[t], v1 = CI[N_CH + t];
    float r0 = v0 * v0, r1 = v1 * v1;
    __shared__ float sm[16][2];
    for (int off = 16; off; off >>= 1) {
        r0 += __shfl_down_sync(0xffffffffu, r0, off);
        r1 += __shfl_down_sync(0xffffffffu, r1, off);
    }
    if ((t & 31) == 0) { sm[t >> 5][0] = r0; sm[t >> 5][1] = r1; }
    __syncthreads();
    __shared__ float nrm[2];
    if (t == 0) {
        float a0 = 0.f, a1 = 0.f;
        for (int i = 0; i < 16; i++) { a0 += sm[i][0]; a1 += sm[i][1]; }
        nrm[0] = fmaxf(sqrtf(a0), 1e-12f);
        nrm[1] = fmaxf(sqrtf(a1), 1e-12f);
        g_cd = 0.f; g_cini = 0.f; g_Ci = 0;
        g_stable = 0; g_nchanged = 0; g_cnt1 = 0;
        g_b1cnt = 0u; g_b1rel = 0u; g_b2cnt = 0u; g_b2rel = 0u; g_done = 0u;
    }
    __syncthreads();
    g_cn[t] = v0 / nrm[0];
    g_cn[N_CH + t] = v1 / nrm[1];
    g_cout[t] = 0.f; g_cout[N_CH + t] = 0.f;
}

// ---------------- one full k-means step in ONE launch ----------------
// 512 blocks x 256 threads, all co-resident (4/SM x 148 SM = 592 slots).
// Phase1: dots (block = (n-chunk, c-split)); barrier; Phase2: labels (warp0,
// 32 pts/block); barrier; Phase3: class sums (block = channel; full or
// incremental); done-counter; last block: center update + state + reset.
__global__ void __launch_bounds__(NT, 4)
k_step(const float4* __restrict__ F4, const float* __restrict__ F, int first) {
    const int t = threadIdx.x, b = blockIdx.x;
    float cdv = *((volatile float*)&g_cd);
    int   civ = *((volatile int*)&g_Ci);
    int   stb = *((volatile int*)&g_stable);
    bool active = first || (cdv >= THRV && civ <= 3);
    if (!active) return;
    if (stb) {
        if (b == 0 && t == 0) {
            if (civ == 0) *((volatile float*)&g_cini) = *((volatile float*)&g_cini) + cdv;
            *((volatile int*)&g_Ci) = civ + 1;
        }
        return;
    }

    // ---------- Phase 1: partial dot products (+ nsq on first) ----------
    {
        int ci = b >> 4, nb = b & 15;      // c-split, n-chunk
        __shared__ float scn0[16], scn1[16];
        if (t < 16) {
            scn0[t] = __ldcg(&g_cn[ci * 16 + t]);
            scn1[t] = __ldcg(&g_cn[N_CH + ci * 16 + t]);
        }
        __syncthreads();
        int nq = nb * 256 + t;             // float4 index over n
        float4 a0 = make_float4(0.f, 0.f, 0.f, 0.f);
        float4 a1 = make_float4(0.f, 0.f, 0.f, 0.f);
        int base = ci * 16 * 4096 + nq;
        if (first) {
            float4 ns = make_float4(0.f, 0.f, 0.f, 0.f);
#pragma unroll
            for (int c = 0; c < 16; c++) {
                float4 f = F4[base + c * 4096];
                float w0 = scn0[c], w1 = scn1[c];
                a0.x += f.x * w0; a0.y += f.y * w0; a0.z += f.z * w0; a0.w += f.w * w0;
                a1.x += f.x * w1; a1.y += f.y * w1; a1.z += f.z * w1; a1.w += f.w * w1;
                ns.x += f.x * f.x; ns.y += f.y * f.y; ns.z += f.z * f.z; ns.w += f.w * f.w;
            }
            __stcg(&((float4*)g_nsqpart)[ci * 4096 + nq], ns);
        } else {
#pragma unroll
            for (int c = 0; c < 16; c++) {
                float4 f = F4[base + c * 4096];
                float w0 = scn0[c], w1 = scn1[c];
                a0.x += f.x * w0; a0.y += f.y * w0; a0.z += f.z * w0; a0.w += f.w * w0;
                a1.x += f.x * w1; a1.y += f.y * w1; a1.z += f.z * w1; a1.w += f.w * w1;
            }
        }
        __stcg(&((float4*)g_dotpart)[(ci * 2 + 0) * 4096 + nq], a0);
        __stcg(&((float4*)g_dotpart)[(ci * 2 + 1) * 4096 + nq], a1);
    }
    // ---------- barrier 1 ----------
    __syncthreads();
    if (t == 0) {
        __threadfence();
        unsigned a = atomicAdd(&g_b1cnt, 1u) + 1u;
        if (a == (unsigned)NBLK) { __threadfence(); atomicExch(&g_b1rel, 1u); }
        else while (*((volatile unsigned*)&g_b1rel) == 0u) __nanosleep(32);
        __threadfence();
    }
    __syncthreads();

    // ---------- Phase 2: labels for this block's 32 points (warp 0) ----------
    if (t < 32) {
        int n = b * 32 + t;
        float d0 = 0.f, d1 = 0.f;
#pragma unroll
        for (int p = 0; p < NSEG; p++) {
            d0 += __ldcg(&g_dotpart[(p * 2 + 0) * N_PTS + n]);
            d1 += __ldcg(&g_dotpart[(p * 2 + 1) * N_PTS + n]);
        }
        float inv;
        if (first) {
            float s = 0.f;
#pragma unroll
            for (int p = 0; p < NSEG; p++) s += __ldcg(&g_nsqpart[p * N_PTS + n]);
            inv = 1.f / fmaxf(sqrtf(s), 1e-12f);
            __stcg(&g_invnorm[n], inv);
        } else {
            inv = __ldcg(&g_invnorm[n]);
        }
        float dd0 = 0.5f * (1.f - inv * d0);
        float dd1 = 0.5f * (1.f - inv * d1);
        int lab = (dd1 < dd0) ? 1 : 0;     // argmin; ties -> 0 (jnp.argmin)
        __stcg(&g_d[n], make_float2(dd0, dd1));
        __stcg(&g_lab[n], lab);
        unsigned m = __ballot_sync(0xffffffffu, lab);
        if (t == 0) {
            unsigned old = __ldcg(&g_labbits[b]);
            unsigned x = first ? 0xffffffffu : (m ^ old);
            __stcg(&g_labbits[b], m);
            __stcg(&g_chgbits[b], x);
            if (x) atomicAdd(&g_nchanged, (int)__popc(x));
            if (m) atomicAdd(&g_cnt1, (int)__popc(m));
        }
    }
    // ---------- barrier 2 ----------
    __syncthreads();
    if (t == 0) {
        __threadfence();
        unsigned a = atomicAdd(&g_b2cnt, 1u) + 1u;
        if (a == (unsigned)NBLK) { __threadfence(); atomicExch(&g_b2rel, 1u); }
        else while (*((volatile unsigned*)&g_b2rel) == 0u) __nanosleep(32);
        __threadfence();
    }
    __syncthreads();

    // ---------- Phase 3: per-class channel sums (block = channel) ----------
    int nch = *((volatile int*)&g_nchanged);       // uniform post-barrier
    bool fullM = (first || nch > THRESH_INC);
    int c = b;
    __shared__ unsigned sbits[NBLK];               // 2KB
    __shared__ float smr[8][4];
    if (fullM) {
        sbits[t] = __ldcg(&g_labbits[t]);
        sbits[t + 256] = __ldcg(&g_labbits[t + 256]);
        __syncthreads();
        const float4* row = F4 + c * (N_PTS / 4);
        float a0 = 0.f, a1 = 0.f;
#pragma unroll
        for (int j = 0; j < 16; j++) {
            int n4 = t + j * 256;
            float4 f = row[n4];
            unsigned nib = (sbits[n4 >> 3] >> ((n4 & 7) * 4)) & 15u;
            if (nib & 1u) a1 += f.x; else a0 += f.x;
            if (nib & 2u) a1 += f.y; else a0 += f.y;
            if (nib & 4u) a1 += f.z; else a0 += f.z;
            if (nib & 8u) a1 += f.w; else a0 += f.w;
        }
        for (int off = 16; off; off >>= 1) {
            a0 += __shfl_down_sync(0xffffffffu, a0, off);
            a1 += __shfl_down_sync(0xffffffffu, a1, off);
        }
        if ((t & 31) == 0) { smr[t >> 5][0] = a0; smr[t >> 5][1] = a1; }
        __syncthreads();
        if (t == 0) {
            float s0 = 0.f, s1 = 0.f;
            for (int i = 0; i < 8; i++) { s0 += smr[i][0]; s1 += smr[i][1]; }
            __stcg(&g_sums[c], s0);
            __stcg(&g_sums[N_CH + c], s1);
        }
    } else if (nch > 0) {
        const float* row = F + c * N_PTS;
        float d0 = 0.f, d1 = 0.f;
        for (int wi = t; wi < NBLK; wi += 256) {
            unsigned chg = __ldcg(&g_chgbits[wi]);
            if (!chg) continue;
            unsigned now = __ldcg(&g_labbits[wi]);
            do {
                int bb = __ffs(chg) - 1; chg &= chg - 1u;
                float f = __ldcg(&row[wi * 32 + bb]);
                if ((now >> bb) & 1u) { d1 += f; d0 -= f; }
                else                  { d1 -= f; d0 += f; }
            } while (chg);
        }
        for (int off = 16; off; off >>= 1) {
            d0 += __shfl_down_sync(0xffffffffu, d0, off);
            d1 += __shfl_down_sync(0xffffffffu, d1, off);
        }
        if ((t & 31) == 0) { smr[t >> 5][0] = d0; smr[t >> 5][1] = d1; }
        __syncthreads();
        if (t == 0) {
            float s0 = 0.f, s1 = 0.f;
            for (int i = 0; i < 8; i++) { s0 += smr[i][0]; s1 += smr[i][1]; }
            __stcg(&g_sums[c], __ldcg(&g_sums[c]) + s0);
            __stcg(&g_sums[N_CH + c], __ldcg(&g_sums[N_CH + c]) + s1);
        }
    }
    // nch==0: sums unchanged; fall through to done-counter

    // ---------- done-counter; last block does update + reset ----------
    __shared__ int isl;
    __syncthreads();
    if (t == 0) {
        __threadfence();
        unsigned a = atomicAdd(&g_done, 1u) + 1u;
        isl = (a == (unsigned)NBLK);
    }
    __syncthreads();
    if (!isl) return;
    __threadfence();
    {
        int c1 = *((volatile int*)&g_cnt1);
        int c0 = N_PTS - c1;
        float inv0 = 1.f / (float)(c0 + 1), inv1 = 1.f / (float)(c1 + 1);
        int ca = t, cb2 = t + 256;
        float s0a = __ldcg(&g_sums[ca]),        s0b = __ldcg(&g_sums[cb2]);
        float s1a = __ldcg(&g_sums[N_CH + ca]), s1b = __ldcg(&g_sums[N_CH + cb2]);
        float nc0a = s0a * inv0, nc0b = s0b * inv0;
        float nc1a = s1a * inv1, nc1b = s1b * inv1;
        float o0a = __ldcg(&g_cn[ca]),        o0b = __ldcg(&g_cn[cb2]);
        float o1a = __ldcg(&g_cn[N_CH + ca]), o1b = __ldcg(&g_cn[N_CH + cb2]);
        __stcg(&g_centers[ca], nc0a);        __stcg(&g_centers[cb2], nc0b);
        __stcg(&g_centers[N_CH + ca], nc1a); __stcg(&g_centers[N_CH + cb2], nc1b);

        float r0 = nc0a * nc0a + nc0b * nc0b;
        float r1 = nc1a * nc1a + nc1b * nc1b;
        float r2 = nc0a * o0a + nc0b * o0b;
        float r3 = nc1a * o1a + nc1b * o1b;
        for (int off = 16; off; off >>= 1) {
            r0 += __shfl_down_sync(0xffffffffu, r0, off);
            r1 += __shfl_down_sync(0xffffffffu, r1, off);
            r2 += __shfl_down_sync(0xffffffffu, r2, off);
            r3 += __shfl_down_sync(0xffffffffu, r3, off);
        }
        if ((t & 31) == 0) { smr[t >> 5][0] = r0; smr[t >> 5][1] = r1; smr[t >> 5][2] = r2; smr[t >> 5][3] = r3; }
        __syncthreads();
        __shared__ float bro[2];
        if (t == 0) {
            float b0 = 0.f, b1 = 0.f, b2 = 0.f, b3 = 0.f;
            for (int i = 0; i < 8; i++) { b0 += smr[i][0]; b1 += smr[i][1]; b2 += smr[i][2]; b3 += smr[i][3]; }
            float nn0 = fmaxf(sqrtf(b0), 1e-12f);
            float nn1 = fmaxf(sqrtf(b1), 1e-12f);
            float cdn = 0.5f * (b2 / nn0 + b3 / nn1);
            if (civ == 0) *((volatile float*)&g_cini) = *((volatile float*)&g_cini) + cdn;
            *((volatile int*)&g_Ci) = civ + 1;
            *((volatile float*)&g_cd) = cdn;
            if (!first && nch == 0) *((volatile int*)&g_stable) = 1;
            *((volatile int*)&g_nchanged) = 0;
            *((volatile int*)&g_cnt1) = 0;
            atomicExch(&g_b1cnt, 0u); atomicExch(&g_b1rel, 0u);
            atomicExch(&g_b2cnt, 0u); atomicExch(&g_b2rel, 0u);
            atomicExch(&g_done, 0u);
            bro[0] = nn0; bro[1] = nn1;
        }
        __syncthreads();
        float in0 = 1.f / bro[0], in1 = 1.f / bro[1];
        __stcg(&g_cn[ca], nc0a * in0);        __stcg(&g_cn[cb2], nc0b * in0);
        __stcg(&g_cn[N_CH + ca], nc1a * in1); __stcg(&g_cn[N_CH + cb2], nc1b * in1);
    }
}

// ---------------- batch snapshot ----------------
__global__ void k_snapshot(int b, float* __restrict__ out) {
    int t = threadIdx.x;
    int n = blockIdx.x * 256 + t;
    int lab = g_lab[n];
    g_dsnap[(b << 14) + n] = g_d[n];
    out[1024 + (b << 14) + n] = (float)lab;
    int ohb = 66560 + (((b << 14) + n) << 1);
    out[ohb]     = lab ? 0.f : 1.f;
    out[ohb + 1] = lab ? 1.f : 0.f;
    if (blockIdx.x == 0) {
        for (int i = t; i < 2 * N_CH; i += 256) g_cout[i] += g_centers[i];
        if (t == 0) g_Ci = 0;                                   // batch boundary reset
    }
}

// ---------------- per-(batch,class) min/max ----------------
__global__ void k_minmax() {
    int b = blockIdx.x >> 1, k = blockIdx.x & 1;
    int t = threadIdx.x;
    float mn = 3.4e38f, mx = -3.4e38f;
    for (int i = t; i < N_PTS; i += 256) {
        float2 dv = g_dsnap[(b << 14) + i];
        float v = k ? dv.y : dv.x;
        mn = fminf(mn, v); mx = fmaxf(mx, v);
    }
    __shared__ float smn[8], smx[8];
    for (int off = 16; off; off >>= 1) {
        mn = fminf(mn, __shfl_down_sync(0xffffffffu, mn, off));
        mx = fmaxf(mx, __shfl_down_sync(0xffffffffu, mx, off));
    }
    if ((t & 31) == 0) { smn[t >> 5] = mn; smx[t >> 5] = mx; }
    __syncthreads();
    if (t == 0) {
        for (int i = 1; i < 8; i++) { mn = fminf(mn, smn[i]); mx = fmaxf(mx, smx[i]); }
        g_mn[blockIdx.x] = mn; g_mx[blockIdx.x] = mx;
    }
}

// ---------------- final ----------------
__global__ void k_final(float* __restrict__ out) {
    int idx = blockIdx.x * 256 + threadIdx.x;   // 65536
    int b = idx >> 14;
    int lab = (int)out[1024 + idx];
    float2 dv = g_dsnap[idx];
    float d = lab ? dv.y : dv.x;
    float rng = g_mx[b * 2 + lab] - g_mn[b * 2 + lab] + 1e-7f;
    out[197632 + idx] = 1.1f + d / rng;
    if (idx < 2 * N_CH) out[idx] = g_cout[idx] * 0.25f;
    if (idx == 0) out[263168] = g_cini * 0.25f;
}

// ---------------- launch ----------------
extern "C" void kernel_launch(void* const* d_in, const int* in_sizes, int n_in,
                              void* d_out, int out_size) {
    const float* F  = (const float*)d_in[0];   // FeatureT [4,512,128,128]
    const float* CI = (const float*)d_in[1];   // centerInit [2,512]
    if (n_in >= 2 && in_sizes[0] < in_sizes[1]) {
        const float* tmp = F; F = CI; CI = tmp;
    }
    float* out = (float*)d_out;
    (void)out_size;

    k_init<<<1, 512>>>(CI);
    for (int s = 0; s < 17; s++) {
        k_step<<<NBLK, NT>>>((const float4*)F, F, (s == 0) ? 1 : 0);
        if (s > 0 && (s & 3) == 0) {
            k_snapshot<<<64, 256>>>(s / 4 - 1, out);
        }
    }
    k_minmax<<<8, 256>>>();
    k_final<<<256, 256>>>(out);
}